// round 16
// baseline (speedup 1.0000x reference)
#include <cuda_runtime.h>
#include <cuda_bf16.h>
#include <cstdint>

#define NB 4
#define NL 2048
#define NE 1024
#define NH 8
#define ND 128
#define NM (NB * NL)
#define ATT_SCALE 0.08838834764831845f

// ---------------------------------------------------------------------------
__device__ __forceinline__ uint32_t smem_to_u32(const void* p) {
    uint32_t a;
    asm("{ .reg .u64 t; cvta.to.shared.u64 t, %1; cvt.u32.u64 %0, t; }"
        : "=r"(a) : "l"(p));
    return a;
}
#define CP_ASYNC_16(dst, src) \
    asm volatile("cp.async.cg.shared.global [%0], [%1], 16;" :: "r"(dst), "l"(src))
#define CP_COMMIT() asm volatile("cp.async.commit_group;" ::: "memory")
#define CP_WAIT(n)  asm volatile("cp.async.wait_group %0;" :: "n"(n) : "memory")

#define LDSM4(R, addr) \
    asm volatile("ldmatrix.sync.aligned.m8n8.x4.shared.b16 {%0,%1,%2,%3}, [%4];" \
        : "=r"((R)[0]), "=r"((R)[1]), "=r"((R)[2]), "=r"((R)[3]) : "r"(addr))
#define LDSM4T(R, addr) \
    asm volatile("ldmatrix.sync.aligned.m8n8.x4.trans.shared.b16 {%0,%1,%2,%3}, [%4];" \
        : "=r"((R)[0]), "=r"((R)[1]), "=r"((R)[2]), "=r"((R)[3]) : "r"(addr))

__device__ __forceinline__ void mma16816(float* c, const uint32_t* a,
                                         uint32_t b0, uint32_t b1) {
    asm volatile("mma.sync.aligned.m16n8k16.row.col.f32.bf16.bf16.f32 "
        "{%0,%1,%2,%3}, {%4,%5,%6,%7}, {%8,%9}, {%0,%1,%2,%3};"
        : "+f"(c[0]), "+f"(c[1]), "+f"(c[2]), "+f"(c[3])
        : "r"(a[0]), "r"(a[1]), "r"(a[2]), "r"(a[3]), "r"(b0), "r"(b1));
}
__device__ __forceinline__ uint32_t pk2(float lo, float hi) {
    uint32_t r;
    asm("cvt.rn.bf16x2.f32 %0, %1, %2;" : "=r"(r) : "f"(hi), "f"(lo));
    return r;
}

// ---------------------------------------------------------------------------
// Scratch
// ---------------------------------------------------------------------------
__device__ __nv_bfloat16 g_Xqh[NM * NE], g_Xql[NM * NE];
__device__ __nv_bfloat16 g_Xkh[NM * NE], g_Xkl[NM * NE];
__device__ __nv_bfloat16 g_WQh[NE * NE], g_WQl[NE * NE];
__device__ __nv_bfloat16 g_WKVh[2 * NE * NE], g_WKVl[2 * NE * NE];  // [WK;WV]
__device__ __nv_bfloat16 g_WFh[NE * NE], g_WFl[NE * NE];
__device__ __nv_bfloat16 g_Qh[NM * NE], g_Ql[NM * NE];   // [b,h,l,d]
__device__ __nv_bfloat16 g_Kh[NM * NE], g_Kl[NM * NE];   // [b,h,l,d]
__device__ __nv_bfloat16 g_Vh[NM * NE], g_Vl[NM * NE];   // [b,h,l,d]
__device__ __nv_bfloat16 g_Ch[NM * NE], g_Cl[NM * NE];   // ctx split

// ---------------------------------------------------------------------------
// Merged vectorized split: grid.y 0 -> qIn, 1 -> kvIn. 4 elems/thread.
__global__ void split2_kernel(const float* __restrict__ qIn,
                              const float* __restrict__ kvIn, int n4) {
    const float* in = blockIdx.y ? kvIn : qIn;
    __nv_bfloat16* hi = blockIdx.y ? g_Xkh : g_Xqh;
    __nv_bfloat16* lo = blockIdx.y ? g_Xkl : g_Xql;
    int i = blockIdx.x * 256 + threadIdx.x;
    if (i < n4) {
        float4 x = ((const float4*)in)[i];
        uint2 H, L;
        H.x = pk2(x.x, x.y);
        H.y = pk2(x.z, x.w);
        const __nv_bfloat16* hp = (const __nv_bfloat16*)&H;
        L.x = pk2(x.x - __bfloat162float(hp[0]), x.y - __bfloat162float(hp[1]));
        L.y = pk2(x.z - __bfloat162float(hp[2]), x.w - __bfloat162float(hp[3]));
        ((uint2*)hi)[i] = H;
        ((uint2*)lo)[i] = L;
    }
}

__global__ void transpose_split4_kernel(const float* __restrict__ W0,
                                        const float* __restrict__ W1,
                                        const float* __restrict__ W2,
                                        const float* __restrict__ W3) {
    const float* in;
    __nv_bfloat16 *oHi, *oLo;
    switch (blockIdx.z) {
        case 0:  in = W0; oHi = g_WQh;  oLo = g_WQl;  break;
        case 1:  in = W1; oHi = g_WKVh; oLo = g_WKVl; break;
        case 2:  in = W2; oHi = g_WKVh + NE * NE; oLo = g_WKVl + NE * NE; break;
        default: in = W3; oHi = g_WFh;  oLo = g_WFl;  break;
    }
    __shared__ float t[32][33];
    const int c0 = blockIdx.x * 32, r0 = blockIdx.y * 32;
    const int x = threadIdx.x, y = threadIdx.y;
#pragma unroll
    for (int j = 0; j < 32; j += 8)
        t[y + j][x] = in[(size_t)(r0 + y + j) * NE + c0 + x];
    __syncthreads();
#pragma unroll
    for (int j = 0; j < 32; j += 8) {
        float v = t[x][y + j];
        __nv_bfloat16 h = __float2bfloat16(v);
        size_t o = (size_t)(c0 + y + j) * NE + r0 + x;
        oHi[o] = h;
        oLo[o] = __float2bfloat16(v - __bfloat162float(h));
    }
}

// ---------------------------------------------------------------------------
// Raw-mma bf16x3 GEMM (round-13 config, unchanged):
// 128 threads, CTA tile 64x128, warps 2x2 (warp tile m32 x n64), K-chunk 32,
// 2-stage cp.async, 3 CTAs/SM, load-all-then-term-major mainloop.
// CMODE 0: fp32 row-major.  CMODE 1: split scatter [b,h,l,d] (Q).
// CMODE 4: split scatter; n<1024 -> K, n>=1024 -> V.
// ---------------------------------------------------------------------------
#define GA_B 5120
#define GB_B 10240
#define GCHUNK2 30720

template <int CMODE>
__global__ __launch_bounds__(128, 3) void gemm_kernel(
    const __nv_bfloat16* __restrict__ Ahi, const __nv_bfloat16* __restrict__ Alo,
    const __nv_bfloat16* __restrict__ Bhi, const __nv_bfloat16* __restrict__ Blo,
    float* __restrict__ C, __nv_bfloat16* __restrict__ Chi,
    __nv_bfloat16* __restrict__ Clo, int Kdim, int lda, int ldb, int ldc)
{
    extern __shared__ char smem[];
    const uint32_t sbase = smem_to_u32(smem);
    const int tid = threadIdx.x;
    const int wid = tid >> 5, lane = tid & 31;
    const int g4 = lane >> 2, t4 = lane & 3;
    const int wm = (wid & 1) * 32;      // warp m offset
    const int wn = (wid >> 1) * 64;     // warp n offset
    const int m0 = blockIdx.y * 64, n0 = blockIdx.x * 128;

    float acc[16][4];
#pragma unroll
    for (int j = 0; j < 16; j++)
#pragma unroll
        for (int e = 0; e < 4; e++) acc[j][e] = 0.f;

    const int nk = Kdim >> 5;
    auto load_chunk = [&](int kc, int buf) {
        const int k0 = kc << 5;
        const uint32_t dbase = sbase + buf * GCHUNK2;
#pragma unroll
        for (int i = tid; i < 1536; i += 128) {
            if (i < 512) {
                const int t = i >> 8, r = (i >> 2) & 63, c = i & 3;
                const __nv_bfloat16* g = (t ? Alo : Ahi)
                    + (size_t)(m0 + r) * lda + k0 + c * 8;
                CP_ASYNC_16(dbase + t * GA_B + r * 80 + c * 16, g);
            } else {
                const int j = i - 512;
                const int t = j >> 9, r = (j >> 2) & 127, c = j & 3;
                const __nv_bfloat16* g = (t ? Blo : Bhi)
                    + (size_t)(n0 + r) * ldb + k0 + c * 8;
                CP_ASYNC_16(dbase + 2 * GA_B + t * GB_B + r * 80 + c * 16, g);
            }
        }
        CP_COMMIT();
    };

    load_chunk(0, 0);
    for (int kc = 0; kc < nk; kc++) {
        const int buf = kc & 1;
        if (kc + 1 < nk) { load_chunk(kc + 1, buf ^ 1); CP_WAIT(1); }
        else             { CP_WAIT(0); }
        __syncthreads();

        const uint32_t abase = sbase + buf * GCHUNK2;
        const uint32_t bbase = abase + 2 * GA_B;

#pragma unroll
        for (int ks = 0; ks < 32; ks += 16) {
            uint32_t ah[2][4], al[2][4], bh[4][4], bl[4][4];
#pragma unroll
            for (int mi = 0; mi < 2; mi++) {
                const uint32_t aaddr = abase
                    + (wm + mi * 16 + ((lane >> 3) & 1) * 8 + (lane & 7)) * 80
                    + (ks + ((lane >> 4) & 1) * 8) * 2;
                LDSM4(ah[mi], aaddr);
                LDSM4(al[mi], aaddr + GA_B);
            }
#pragma unroll
            for (int g2 = 0; g2 < 4; g2++) {
                const uint32_t baddr = bbase
                    + (wn + g2 * 16 + ((lane >> 4) & 1) * 8 + (lane & 7)) * 80
                    + (ks + ((lane >> 3) & 1) * 8) * 2;
                LDSM4(bh[g2], baddr);
                LDSM4(bl[g2], baddr + GB_B);
            }
#pragma unroll
            for (int g2 = 0; g2 < 4; g2++)
#pragma unroll
                for (int mi = 0; mi < 2; mi++) {
                    mma16816(acc[mi * 8 + 2 * g2],     ah[mi], bh[g2][0], bh[g2][1]);
                    mma16816(acc[mi * 8 + 2 * g2 + 1], ah[mi], bh[g2][2], bh[g2][3]);
                }
#pragma unroll
            for (int g2 = 0; g2 < 4; g2++)
#pragma unroll
                for (int mi = 0; mi < 2; mi++) {
                    mma16816(acc[mi * 8 + 2 * g2],     ah[mi], bl[g2][0], bl[g2][1]);
                    mma16816(acc[mi * 8 + 2 * g2 + 1], ah[mi], bl[g2][2], bl[g2][3]);
                }
#pragma unroll
            for (int g2 = 0; g2 < 4; g2++)
#pragma unroll
                for (int mi = 0; mi < 2; mi++) {
                    mma16816(acc[mi * 8 + 2 * g2],     al[mi], bh[g2][0], bh[g2][1]);
                    mma16816(acc[mi * 8 + 2 * g2 + 1], al[mi], bh[g2][2], bh[g2][3]);
                }
        }
        __syncthreads();
    }

    // ---- register epilogue ----
#pragma unroll
    for (int mi = 0; mi < 2; mi++) {
        const int rA = m0 + wm + mi * 16 + g4;
#pragma unroll
        for (int nj = 0; nj < 8; nj++) {
            const int idx = mi * 8 + nj;
            const int col = wn + nj * 8 + 2 * t4;
            const float c0 = acc[idx][0], c1 = acc[idx][1];
            const float c2 = acc[idx][2], c3 = acc[idx][3];
            if (CMODE == 0) {
                float2 v0 = {c0, c1}, v1 = {c2, c3};
                *(float2*)&C[(size_t)rA * ldc + n0 + col] = v0;
                *(float2*)&C[(size_t)(rA + 8) * ldc + n0 + col] = v1;
            } else {
                const int n = (CMODE == 4) ? ((n0 + col) & 1023) : (n0 + col);
                const bool isV = (CMODE == 4) && (n0 >= 1024);
                __nv_bfloat16* Hh = (CMODE == 1) ? g_Qh : (isV ? g_Vh : g_Kh);
                __nv_bfloat16* Hl = (CMODE == 1) ? g_Ql : (isV ? g_Vl : g_Kl);
#pragma unroll
                for (int rr = 0; rr < 2; rr++) {
                    const int m = rA + rr * 8;
                    const float a0 = rr ? c2 : c0, a1 = rr ? c3 : c1;
                    const size_t gi = (((size_t)(m >> 11) * 8 + (n >> 7)) * 2048
                                       + (m & 2047)) * 128 + (n & 127);
                    const uint32_t hh = pk2(a0, a1);
                    *(uint32_t*)(Hh + gi) = hh;
                    const float h0 = __bfloat162float(*(__nv_bfloat16*)&hh);
                    const float h1 = __bfloat162float(((__nv_bfloat16*)&hh)[1]);
                    *(uint32_t*)(Hl + gi) = pk2(a0 - h0, a1 - h1);
                }
            }
        }
    }
}

// ---------------------------------------------------------------------------
// FA2-style flash attention, round 16: q-tile 128, kv-tile 64, 256 threads
// (8 warps, each m16 x kv64 — round-14 per-warp work shape), 2 CTAs/SM.
// Register-resident S/P/lsum; interleaved S-loop (low frag pressure) to fit
// the 128-reg cap; PV 2-batch term-major.
// smem: Qh/Ql [128][136] (69632), KV hi/lo [64][136] (34816), mask 128x64B.
// ---------------------------------------------------------------------------
#define FO_QL 34816
#define FO_KV 69632            // hi at +0, lo at +17408
#define FO_M  104448           // mask tile 128 x 64 B
#define FSMEM 112640

__global__ __launch_bounds__(256, 2) void flash_kernel(const unsigned char* __restrict__ mask)
{
    extern __shared__ char sm[];
    const uint32_t sbase = smem_to_u32(sm);
    const unsigned char* smu = (const unsigned char*)sm;
    const int tid = threadIdx.x;
    const int wid = tid >> 5, lane = tid & 31;
    const int g4 = lane >> 2, t4 = lane & 3;
    const int wm = wid * 16;               // 8 warps x 16 rows = 128
    const int q0 = blockIdx.x * 128;
    const int bh = blockIdx.y;
    const int b = bh >> 3, h = bh & 7;
    const size_t bhoff = (size_t)bh * NL * ND;
    const size_t mbase = ((size_t)bh * NL + q0) * NL;

    // prologue: Q hi/lo (128 rows) + K tile 0 + mask tile 0
#pragma unroll
    for (int i = tid; i < 4096; i += 256) {
        const int t = i >> 11, r = (i >> 4) & 127, c = i & 15;
        const __nv_bfloat16* g = (t ? g_Ql : g_Qh) + bhoff + (size_t)(q0 + r) * 128 + c * 8;
        CP_ASYNC_16(sbase + t * 34816 + r * 272 + c * 16, g);
    }
#pragma unroll
    for (int i = tid; i < 2048; i += 256) {
        const int t = i >> 10, r = (i >> 4) & 63, c = i & 15;
        const __nv_bfloat16* g = (t ? g_Kl : g_Kh) + bhoff + (size_t)r * 128 + c * 8;
        CP_ASYNC_16(sbase + FO_KV + t * 17408 + r * 272 + c * 16, g);
    }
#pragma unroll
    for (int i = tid; i < 512; i += 256) {
        const int r = i >> 2, c = i & 3;
        CP_ASYNC_16(sbase + FO_M + r * 64 + c * 16, mask + mbase + (size_t)r * NL + c * 16);
    }
    CP_COMMIT();

    float oacc[16][4];
#pragma unroll
    for (int j = 0; j < 16; j++)
#pragma unroll
        for (int e = 0; e < 4; e++) oacc[j][e] = 0.f;
    float l0 = 0.f, l1 = 0.f;

    for (int kt = 0; kt < 32; kt++) {
        CP_WAIT(0);
        __syncthreads();   // K + mask ready; prev V consumed

        // per-warp mask-any: warp's 16 rows x 64 B = 1024 B = 32 B/lane
        const uint4 mA = *(const uint4*)(smu + FO_M + wm * 64 + lane * 32);
        const uint4 mB = *(const uint4*)(smu + FO_M + wm * 64 + lane * 32 + 16);
        const bool anymask = __any_sync(0xffffffffu,
            (mA.x | mA.y | mA.z | mA.w | mB.x | mB.y | mB.z | mB.w) != 0);

        // ---- S = Q K^T (bf16x3), interleaved (low frag pressure) ----
        float sc[8][4];
#pragma unroll
        for (int j = 0; j < 8; j++)
#pragma unroll
            for (int e = 0; e < 4; e++) sc[j][e] = 0.f;

#pragma unroll
        for (int ks = 0; ks < 128; ks += 16) {
            uint32_t qh[4], ql[4];
            const uint32_t qaddr = sbase
                + (wm + ((lane >> 3) & 1) * 8 + (lane & 7)) * 272
                + (ks + ((lane >> 4) & 1) * 8) * 2;
            LDSM4(qh, qaddr);
            LDSM4(ql, qaddr + FO_QL);
#pragma unroll
            for (int g2 = 0; g2 < 4; g2++) {
                uint32_t kh[4], kl[4];
                const uint32_t kaddr = sbase + FO_KV
                    + (g2 * 16 + ((lane >> 4) & 1) * 8 + (lane & 7)) * 272
                    + (ks + ((lane >> 3) & 1) * 8) * 2;
                LDSM4(kh, kaddr);
                LDSM4(kl, kaddr + 17408);
                mma16816(sc[2 * g2],     qh, kh[0], kh[1]);
                mma16816(sc[2 * g2 + 1], qh, kh[2], kh[3]);
                mma16816(sc[2 * g2],     qh, kl[0], kl[1]);
                mma16816(sc[2 * g2 + 1], qh, kl[2], kl[3]);
                mma16816(sc[2 * g2],     ql, kh[0], kh[1]);
                mma16816(sc[2 * g2 + 1], ql, kh[2], kh[3]);
            }
        }
        __syncthreads();   // K consumed; buffer free for V

        // ---- issue V load (overlaps softmax) ----
#pragma unroll
        for (int i = tid; i < 2048; i += 256) {
            const int t = i >> 10, r = (i >> 4) & 63, c = i & 15;
            const __nv_bfloat16* g = (t ? g_Vl : g_Vh) + bhoff
                + (size_t)(kt * 64 + r) * 128 + c * 8;
            CP_ASYNC_16(sbase + FO_KV + t * 17408 + r * 272 + c * 16, g);
        }
        CP_COMMIT();

        // ---- register softmax + P packing ----
        uint32_t pha[16], pla[16];
        float l0a = 0.f, l1a = 0.f;
#pragma unroll
        for (int j = 0; j < 8; j++) {
            float s0 = sc[j][0] * ATT_SCALE, s1 = sc[j][1] * ATT_SCALE;
            float s2 = sc[j][2] * ATT_SCALE, s3 = sc[j][3] * ATT_SCALE;
            if (anymask) {
                const int c0 = 8 * j + 2 * t4;
                if (smu[FO_M + (wm + g4) * 64 + c0])         s0 = -1e9f;
                if (smu[FO_M + (wm + g4) * 64 + c0 + 1])     s1 = -1e9f;
                if (smu[FO_M + (wm + g4 + 8) * 64 + c0])     s2 = -1e9f;
                if (smu[FO_M + (wm + g4 + 8) * 64 + c0 + 1]) s3 = -1e9f;
            }
            const float p0 = __expf(s0), p1 = __expf(s1);
            const float p2 = __expf(s2), p3 = __expf(s3);
            l0a += p0 + p1;
            l1a += p2 + p3;
            const float h0 = __bfloat162float(__float2bfloat16(p0));
            const float h1 = __bfloat162float(__float2bfloat16(p1));
            const float h2 = __bfloat162float(__float2bfloat16(p2));
            const float h3 = __bfloat162float(__float2bfloat16(p3));
            const int base = 4 * (j >> 1) + (j & 1) * 2;
            pha[base]     = pk2(p0, p1);
            pha[base + 1] = pk2(p2, p3);
            pla[base]     = pk2(p0 - h0, p1 - h1);
            pla[base + 1] = pk2(p2 - h2, p3 - h3);
        }
        l0a += __shfl_xor_sync(0xffffffffu, l0a, 1);
        l0a += __shfl_xor_sync(0xffffffffu, l0a, 2);
        l1a += __shfl_xor_sync(0xffffffffu, l1a, 1);
        l1a += __shfl_xor_sync(0xffffffffu, l1a, 2);
        l0 += l0a;
        l1 += l1a;

        CP_WAIT(0);
        __syncthreads();   // V ready

        // ---- O += P V (bf16x3): 2-batch V frags, term-major ----
#pragma unroll
        for (int q = 0; q < 4; q++) {
#pragma unroll
            for (int h2b = 0; h2b < 8; h2b += 2) {
                uint32_t vh[2][4], vl[2][4];
#pragma unroll
                for (int j = 0; j < 2; j++) {
                    const int h2 = h2b + j;
                    const uint32_t vaddr = sbase + FO_KV
                        + (16 * q + ((lane >> 3) & 1) * 8 + (lane & 7)) * 272
                        + (16 * h2 + ((lane >> 4) & 1) * 8) * 2;
                    LDSM4T(vh[j], vaddr);
                    LDSM4T(vl[j], vaddr + 17408);
                }
#pragma unroll
                for (int j = 0; j < 2; j++) {
                    const int h2 = h2b + j;
                    mma16816(oacc[2 * h2],     &pha[4 * q], vh[j][0], vh[j][1]);
                    mma16816(oacc[2 * h2 + 1], &pha[4 * q], vh[j][2], vh[j][3]);
                }
#pragma unroll
                for (int j = 0; j < 2; j++) {
                    const int h2 = h2b + j;
                    mma16816(oacc[2 * h2],     &pha[4 * q], vl[j][0], vl[j][1]);
                    mma16816(oacc[2 * h2 + 1], &pha[4 * q], vl[j][2], vl[j][3]);
                }
#pragma unroll
                for (int j = 0; j < 2; j++) {
                    const int h2 = h2b + j;
                    mma16816(oacc[2 * h2],     &pla[4 * q], vh[j][0], vh[j][1]);
                    mma16816(oacc[2 * h2 + 1], &pla[4 * q], vh[j][2], vh[j][3]);
                }
            }
        }
        __syncthreads();   // V consumed; buffer free for next K

        // ---- issue next K + mask ----
        if (kt + 1 < 32) {
#pragma unroll
            for (int i = tid; i < 2048; i += 256) {
                const int t = i >> 10, r = (i >> 4) & 63, c = i & 15;
                const __nv_bfloat16* g = (t ? g_Kl : g_Kh) + bhoff
                    + (size_t)((kt + 1) * 64 + r) * 128 + c * 8;
                CP_ASYNC_16(sbase + FO_KV + t * 17408 + r * 272 + c * 16, g);
            }
#pragma unroll
            for (int i = tid; i < 512; i += 256) {
                const int r = i >> 2, c = i & 3;
                CP_ASYNC_16(sbase + FO_M + r * 64 + c * 16,
                            mask + mbase + (size_t)r * NL + (kt + 1) * 64 + c * 16);
            }
            CP_COMMIT();
        }
    }

    // ---- epilogue: normalize, split, write ctx from registers ----
    const float inv0 = 1.f / l0, inv1 = 1.f / l1;
    const size_t row0 = (size_t)(b * NL + q0 + wm + g4);
    const size_t o0 = row0 * 1024 + h * 128 + 2 * t4;
    const size_t o1 = o0 + 8 * 1024;
#pragma unroll
    for (int j = 0; j < 16; j++) {
        const float v0 = oacc[j][0] * inv0, v1 = oacc[j][1] * inv0;
        const float v2 = oacc[j][2] * inv1, v3 = oacc[j][3] * inv1;
        const __nv_bfloat162 h0 = __floats2bfloat162_rn(v0, v1);
        const __nv_bfloat162 h2 = __floats2bfloat162_rn(v2, v3);
        *(__nv_bfloat162*)(g_Ch + o0 + 8 * j) = h0;
        *(__nv_bfloat162*)(g_Ch + o1 + 8 * j) = h2;
        const __nv_bfloat162 r0 = __floats2bfloat162_rn(
            v0 - __bfloat162float(h0.x), v1 - __bfloat162float(h0.y));
        const __nv_bfloat162 r2 = __floats2bfloat162_rn(
            v2 - __bfloat162float(h2.x), v3 - __bfloat162float(h2.y));
        *(__nv_bfloat162*)(g_Cl + o0 + 8 * j) = r0;
        *(__nv_bfloat162*)(g_Cl + o1 + 8 * j) = r2;
    }
}

// ---------------------------------------------------------------------------
extern "C" void kernel_launch(void* const* d_in, const int* in_sizes, int n_in,
                              void* d_out, int out_size)
{
    const float* qIn  = (const float*)d_in[0];
    const float* kvIn = (const float*)d_in[1];
    const unsigned char* mask = (const unsigned char*)d_in[2];
    const float* W_Q  = (const float*)d_in[3];
    const float* W_K  = (const float*)d_in[4];
    const float* W_V  = (const float*)d_in[5];
    const float* W_fc = (const float*)d_in[6];
    float* out = (float*)d_out;

    __nv_bfloat16 *pXqh, *pXql, *pXkh, *pXkl;
    __nv_bfloat16 *pWQh, *pWQl, *pWKVh, *pWKVl, *pWFh, *pWFl;
    __nv_bfloat16 *pQh, *pQl, *pCh, *pCl;
    cudaGetSymbolAddress((void**)&pXqh, g_Xqh);   cudaGetSymbolAddress((void**)&pXql, g_Xql);
    cudaGetSymbolAddress((void**)&pXkh, g_Xkh);   cudaGetSymbolAddress((void**)&pXkl, g_Xkl);
    cudaGetSymbolAddress((void**)&pWQh, g_WQh);   cudaGetSymbolAddress((void**)&pWQl, g_WQl);
    cudaGetSymbolAddress((void**)&pWKVh, g_WKVh); cudaGetSymbolAddress((void**)&pWKVl, g_WKVl);
    cudaGetSymbolAddress((void**)&pWFh, g_WFh);   cudaGetSymbolAddress((void**)&pWFl, g_WFl);
    cudaGetSymbolAddress((void**)&pQh,  g_Qh);    cudaGetSymbolAddress((void**)&pQl,  g_Ql);
    cudaGetSymbolAddress((void**)&pCh,  g_Ch);    cudaGetSymbolAddress((void**)&pCl,  g_Cl);

    const int NTOT = NM * NE;
    const int SMEM_GEMM = 2 * GCHUNK2;   // 61440
    cudaFuncSetAttribute(gemm_kernel<0>, cudaFuncAttributeMaxDynamicSharedMemorySize, SMEM_GEMM);
    cudaFuncSetAttribute(gemm_kernel<1>, cudaFuncAttributeMaxDynamicSharedMemorySize, SMEM_GEMM);
    cudaFuncSetAttribute(gemm_kernel<4>, cudaFuncAttributeMaxDynamicSharedMemorySize, SMEM_GEMM);
    cudaFuncSetAttribute(flash_kernel,   cudaFuncAttributeMaxDynamicSharedMemorySize, FSMEM);

    // 1) splits
    split2_kernel<<<dim3(NTOT / 1024, 2), 256>>>(qIn, kvIn, NTOT / 4);
    transpose_split4_kernel<<<dim3(32, 32, 4), dim3(32, 8)>>>(W_Q, W_K, W_V, W_fc);

    // 2) projections: Q (N=1024) and fused K|V (N=2048)
    gemm_kernel<1><<<dim3(8, 128), 128, SMEM_GEMM>>>(
        pXqh, pXql, pWQh, pWQl, nullptr, pQh, pQl, 1024, 1024, 1024, 0);
    gemm_kernel<4><<<dim3(16, 128), 128, SMEM_GEMM>>>(
        pXkh, pXkl, pWKVh, pWKVl, nullptr, nullptr, nullptr, 1024, 1024, 1024, 0);

    // 3) fused attention -> split ctx [b*l, h*128+d]
    flash_kernel<<<dim3(16, 32), 256, FSMEM>>>(mask);

    // 4) out = ctx W_fc
    gemm_kernel<0><<<dim3(8, 128), 128, SMEM_GEMM>>>(
        pCh, pCl, pWFh, pWFl, out, nullptr, nullptr, 1024, 1024, 1024, 1024);
}

// round 17
// speedup vs baseline: 1.0605x; 1.0605x over previous
#include <cuda_runtime.h>
#include <cuda_bf16.h>
#include <cstdint>

#define NB 4
#define NL 2048
#define NE 1024
#define NH 8
#define ND 128
#define NM (NB * NL)
#define ATT_SCALE 0.08838834764831845f

// ---------------------------------------------------------------------------
__device__ __forceinline__ uint32_t smem_to_u32(const void* p) {
    uint32_t a;
    asm("{ .reg .u64 t; cvta.to.shared.u64 t, %1; cvt.u32.u64 %0, t; }"
        : "=r"(a) : "l"(p));
    return a;
}
#define CP_ASYNC_16(dst, src) \
    asm volatile("cp.async.cg.shared.global [%0], [%1], 16;" :: "r"(dst), "l"(src))
#define CP_COMMIT() asm volatile("cp.async.commit_group;" ::: "memory")
#define CP_WAIT(n)  asm volatile("cp.async.wait_group %0;" :: "n"(n) : "memory")

#define LDSM4(R, addr) \
    asm volatile("ldmatrix.sync.aligned.m8n8.x4.shared.b16 {%0,%1,%2,%3}, [%4];" \
        : "=r"((R)[0]), "=r"((R)[1]), "=r"((R)[2]), "=r"((R)[3]) : "r"(addr))
#define LDSM4T(R, addr) \
    asm volatile("ldmatrix.sync.aligned.m8n8.x4.trans.shared.b16 {%0,%1,%2,%3}, [%4];" \
        : "=r"((R)[0]), "=r"((R)[1]), "=r"((R)[2]), "=r"((R)[3]) : "r"(addr))

__device__ __forceinline__ void mma16816(float* c, const uint32_t* a,
                                         uint32_t b0, uint32_t b1) {
    asm volatile("mma.sync.aligned.m16n8k16.row.col.f32.bf16.bf16.f32 "
        "{%0,%1,%2,%3}, {%4,%5,%6,%7}, {%8,%9}, {%0,%1,%2,%3};"
        : "+f"(c[0]), "+f"(c[1]), "+f"(c[2]), "+f"(c[3])
        : "r"(a[0]), "r"(a[1]), "r"(a[2]), "r"(a[3]), "r"(b0), "r"(b1));
}
__device__ __forceinline__ uint32_t pk2(float lo, float hi) {
    uint32_t r;
    asm("cvt.rn.bf16x2.f32 %0, %1, %2;" : "=r"(r) : "f"(hi), "f"(lo));
    return r;
}

// ---------------------------------------------------------------------------
// Scratch
// ---------------------------------------------------------------------------
__device__ __nv_bfloat16 g_Xqh[NM * NE], g_Xql[NM * NE];
__device__ __nv_bfloat16 g_Xkh[NM * NE], g_Xkl[NM * NE];
__device__ __nv_bfloat16 g_WQh[NE * NE], g_WQl[NE * NE];
__device__ __nv_bfloat16 g_WKVh[2 * NE * NE], g_WKVl[2 * NE * NE];  // [WK;WV]
__device__ __nv_bfloat16 g_WFh[NE * NE], g_WFl[NE * NE];
__device__ __nv_bfloat16 g_Qh[NM * NE], g_Ql[NM * NE];   // [b,h,l,d]
__device__ __nv_bfloat16 g_Kh[NM * NE], g_Kl[NM * NE];   // [b,h,l,d]
__device__ __nv_bfloat16 g_Vh[NM * NE], g_Vl[NM * NE];   // [b,h,l,d]
__device__ __nv_bfloat16 g_Ch[NM * NE], g_Cl[NM * NE];   // ctx split

// ---------------------------------------------------------------------------
// Merged vectorized split: grid.y 0 -> qIn, 1 -> kvIn. 4 elems/thread.
__global__ void split2_kernel(const float* __restrict__ qIn,
                              const float* __restrict__ kvIn, int n4) {
    const float* in = blockIdx.y ? kvIn : qIn;
    __nv_bfloat16* hi = blockIdx.y ? g_Xkh : g_Xqh;
    __nv_bfloat16* lo = blockIdx.y ? g_Xkl : g_Xql;
    int i = blockIdx.x * 256 + threadIdx.x;
    if (i < n4) {
        float4 x = ((const float4*)in)[i];
        uint2 H, L;
        H.x = pk2(x.x, x.y);
        H.y = pk2(x.z, x.w);
        const __nv_bfloat16* hp = (const __nv_bfloat16*)&H;
        L.x = pk2(x.x - __bfloat162float(hp[0]), x.y - __bfloat162float(hp[1]));
        L.y = pk2(x.z - __bfloat162float(hp[2]), x.w - __bfloat162float(hp[3]));
        ((uint2*)hi)[i] = H;
        ((uint2*)lo)[i] = L;
    }
}

__global__ void transpose_split4_kernel(const float* __restrict__ W0,
                                        const float* __restrict__ W1,
                                        const float* __restrict__ W2,
                                        const float* __restrict__ W3) {
    const float* in;
    __nv_bfloat16 *oHi, *oLo;
    switch (blockIdx.z) {
        case 0:  in = W0; oHi = g_WQh;  oLo = g_WQl;  break;
        case 1:  in = W1; oHi = g_WKVh; oLo = g_WKVl; break;
        case 2:  in = W2; oHi = g_WKVh + NE * NE; oLo = g_WKVl + NE * NE; break;
        default: in = W3; oHi = g_WFh;  oLo = g_WFl;  break;
    }
    __shared__ float t[32][33];
    const int c0 = blockIdx.x * 32, r0 = blockIdx.y * 32;
    const int x = threadIdx.x, y = threadIdx.y;
#pragma unroll
    for (int j = 0; j < 32; j += 8)
        t[y + j][x] = in[(size_t)(r0 + y + j) * NE + c0 + x];
    __syncthreads();
#pragma unroll
    for (int j = 0; j < 32; j += 8) {
        float v = t[x][y + j];
        __nv_bfloat16 h = __float2bfloat16(v);
        size_t o = (size_t)(c0 + y + j) * NE + r0 + x;
        oHi[o] = h;
        oLo[o] = __float2bfloat16(v - __bfloat162float(h));
    }
}

// ---------------------------------------------------------------------------
// Raw-mma bf16x3 GEMM (round-13 config, unchanged):
// 128 threads, CTA tile 64x128, warps 2x2 (warp tile m32 x n64), K-chunk 32,
// 2-stage cp.async, 3 CTAs/SM, load-all-then-term-major mainloop.
// CMODE 0: fp32 row-major.  CMODE 1: split scatter [b,h,l,d] (Q).
// CMODE 4: split scatter; n<1024 -> K, n>=1024 -> V.
// ---------------------------------------------------------------------------
#define GA_B 5120
#define GB_B 10240
#define GCHUNK2 30720

template <int CMODE>
__global__ __launch_bounds__(128, 3) void gemm_kernel(
    const __nv_bfloat16* __restrict__ Ahi, const __nv_bfloat16* __restrict__ Alo,
    const __nv_bfloat16* __restrict__ Bhi, const __nv_bfloat16* __restrict__ Blo,
    float* __restrict__ C, __nv_bfloat16* __restrict__ Chi,
    __nv_bfloat16* __restrict__ Clo, int Kdim, int lda, int ldb, int ldc)
{
    extern __shared__ char smem[];
    const uint32_t sbase = smem_to_u32(smem);
    const int tid = threadIdx.x;
    const int wid = tid >> 5, lane = tid & 31;
    const int g4 = lane >> 2, t4 = lane & 3;
    const int wm = (wid & 1) * 32;
    const int wn = (wid >> 1) * 64;
    const int m0 = blockIdx.y * 64, n0 = blockIdx.x * 128;

    float acc[16][4];
#pragma unroll
    for (int j = 0; j < 16; j++)
#pragma unroll
        for (int e = 0; e < 4; e++) acc[j][e] = 0.f;

    const int nk = Kdim >> 5;
    auto load_chunk = [&](int kc, int buf) {
        const int k0 = kc << 5;
        const uint32_t dbase = sbase + buf * GCHUNK2;
#pragma unroll
        for (int i = tid; i < 1536; i += 128) {
            if (i < 512) {
                const int t = i >> 8, r = (i >> 2) & 63, c = i & 3;
                const __nv_bfloat16* g = (t ? Alo : Ahi)
                    + (size_t)(m0 + r) * lda + k0 + c * 8;
                CP_ASYNC_16(dbase + t * GA_B + r * 80 + c * 16, g);
            } else {
                const int j = i - 512;
                const int t = j >> 9, r = (j >> 2) & 127, c = j & 3;
                const __nv_bfloat16* g = (t ? Blo : Bhi)
                    + (size_t)(n0 + r) * ldb + k0 + c * 8;
                CP_ASYNC_16(dbase + 2 * GA_B + t * GB_B + r * 80 + c * 16, g);
            }
        }
        CP_COMMIT();
    };

    load_chunk(0, 0);
    for (int kc = 0; kc < nk; kc++) {
        const int buf = kc & 1;
        if (kc + 1 < nk) { load_chunk(kc + 1, buf ^ 1); CP_WAIT(1); }
        else             { CP_WAIT(0); }
        __syncthreads();

        const uint32_t abase = sbase + buf * GCHUNK2;
        const uint32_t bbase = abase + 2 * GA_B;

#pragma unroll
        for (int ks = 0; ks < 32; ks += 16) {
            uint32_t ah[2][4], al[2][4], bh[4][4], bl[4][4];
#pragma unroll
            for (int mi = 0; mi < 2; mi++) {
                const uint32_t aaddr = abase
                    + (wm + mi * 16 + ((lane >> 3) & 1) * 8 + (lane & 7)) * 80
                    + (ks + ((lane >> 4) & 1) * 8) * 2;
                LDSM4(ah[mi], aaddr);
                LDSM4(al[mi], aaddr + GA_B);
            }
#pragma unroll
            for (int g2 = 0; g2 < 4; g2++) {
                const uint32_t baddr = bbase
                    + (wn + g2 * 16 + ((lane >> 4) & 1) * 8 + (lane & 7)) * 80
                    + (ks + ((lane >> 3) & 1) * 8) * 2;
                LDSM4(bh[g2], baddr);
                LDSM4(bl[g2], baddr + GB_B);
            }
#pragma unroll
            for (int g2 = 0; g2 < 4; g2++)
#pragma unroll
                for (int mi = 0; mi < 2; mi++) {
                    mma16816(acc[mi * 8 + 2 * g2],     ah[mi], bh[g2][0], bh[g2][1]);
                    mma16816(acc[mi * 8 + 2 * g2 + 1], ah[mi], bh[g2][2], bh[g2][3]);
                }
#pragma unroll
            for (int g2 = 0; g2 < 4; g2++)
#pragma unroll
                for (int mi = 0; mi < 2; mi++) {
                    mma16816(acc[mi * 8 + 2 * g2],     ah[mi], bl[g2][0], bl[g2][1]);
                    mma16816(acc[mi * 8 + 2 * g2 + 1], ah[mi], bl[g2][2], bl[g2][3]);
                }
#pragma unroll
            for (int g2 = 0; g2 < 4; g2++)
#pragma unroll
                for (int mi = 0; mi < 2; mi++) {
                    mma16816(acc[mi * 8 + 2 * g2],     al[mi], bh[g2][0], bh[g2][1]);
                    mma16816(acc[mi * 8 + 2 * g2 + 1], al[mi], bh[g2][2], bh[g2][3]);
                }
        }
        __syncthreads();
    }

    // ---- register epilogue ----
#pragma unroll
    for (int mi = 0; mi < 2; mi++) {
        const int rA = m0 + wm + mi * 16 + g4;
#pragma unroll
        for (int nj = 0; nj < 8; nj++) {
            const int idx = mi * 8 + nj;
            const int col = wn + nj * 8 + 2 * t4;
            const float c0 = acc[idx][0], c1 = acc[idx][1];
            const float c2 = acc[idx][2], c3 = acc[idx][3];
            if (CMODE == 0) {
                float2 v0 = {c0, c1}, v1 = {c2, c3};
                *(float2*)&C[(size_t)rA * ldc + n0 + col] = v0;
                *(float2*)&C[(size_t)(rA + 8) * ldc + n0 + col] = v1;
            } else {
                const int n = (CMODE == 4) ? ((n0 + col) & 1023) : (n0 + col);
                const bool isV = (CMODE == 4) && (n0 >= 1024);
                __nv_bfloat16* Hh = (CMODE == 1) ? g_Qh : (isV ? g_Vh : g_Kh);
                __nv_bfloat16* Hl = (CMODE == 1) ? g_Ql : (isV ? g_Vl : g_Kl);
#pragma unroll
                for (int rr = 0; rr < 2; rr++) {
                    const int m = rA + rr * 8;
                    const float a0 = rr ? c2 : c0, a1 = rr ? c3 : c1;
                    const size_t gi = (((size_t)(m >> 11) * 8 + (n >> 7)) * 2048
                                       + (m & 2047)) * 128 + (n & 127);
                    const uint32_t hh = pk2(a0, a1);
                    *(uint32_t*)(Hh + gi) = hh;
                    const float h0 = __bfloat162float(*(__nv_bfloat16*)&hh);
                    const float h1 = __bfloat162float(((__nv_bfloat16*)&hh)[1]);
                    *(uint32_t*)(Hl + gi) = pk2(a0 - h0, a1 - h1);
                }
            }
        }
    }
}

// ---------------------------------------------------------------------------
// FA2-style flash attention (round-14 config + split-K prefetch):
// q-tile 64, kv-tile 64, 128 threads, 3 CTAs/SM, register-resident S/P/lsum,
// term-major MMA order.  K(t+1) issued in two halves interleaved with PV
// (rows 0..31 after q=0,1 consume V rows 0..31; rows 32..63 after q=2,3).
// ---------------------------------------------------------------------------
#define FO_QL 17408
#define FO_KV 34816            // hi at +0, lo at +17408
#define FO_M  69632
#define FSMEM 73728

__global__ __launch_bounds__(128, 3) void flash_kernel(const unsigned char* __restrict__ mask)
{
    extern __shared__ char sm[];
    const uint32_t sbase = smem_to_u32(sm);
    const unsigned char* smu = (const unsigned char*)sm;
    const int tid = threadIdx.x;
    const int wid = tid >> 5, lane = tid & 31;
    const int g4 = lane >> 2, t4 = lane & 3;
    const int wm = wid * 16;
    const int q0 = blockIdx.x * 64;
    const int bh = blockIdx.y;
    const int b = bh >> 3, h = bh & 7;
    const size_t bhoff = (size_t)bh * NL * ND;
    const size_t mbase = ((size_t)bh * NL + q0) * NL;

    // prologue: Q hi/lo + K tile 0 + mask tile 0
#pragma unroll
    for (int i = tid; i < 2048; i += 128) {
        const int t = i >> 10, r = (i >> 4) & 63, c = i & 15;
        const __nv_bfloat16* g = (t ? g_Ql : g_Qh) + bhoff + (size_t)(q0 + r) * 128 + c * 8;
        CP_ASYNC_16(sbase + t * 17408 + r * 272 + c * 16, g);
    }
#pragma unroll
    for (int i = tid; i < 2048; i += 128) {
        const int t = i >> 10, r = (i >> 4) & 63, c = i & 15;
        const __nv_bfloat16* g = (t ? g_Kl : g_Kh) + bhoff + (size_t)r * 128 + c * 8;
        CP_ASYNC_16(sbase + FO_KV + t * 17408 + r * 272 + c * 16, g);
    }
#pragma unroll
    for (int i = tid; i < 256; i += 128) {
        const int r = i >> 2, c = i & 3;
        CP_ASYNC_16(sbase + FO_M + r * 64 + c * 16, mask + mbase + (size_t)r * NL + c * 16);
    }
    CP_COMMIT();

    float oacc[16][4];
#pragma unroll
    for (int j = 0; j < 16; j++)
#pragma unroll
        for (int e = 0; e < 4; e++) oacc[j][e] = 0.f;
    float l0 = 0.f, l1 = 0.f;

    for (int kt = 0; kt < 32; kt++) {
        CP_WAIT(0);
        __syncthreads();   // K + mask ready; prev V consumed

        const uint4 mA = *(const uint4*)(smu + FO_M + wm * 64 + lane * 32);
        const uint4 mB = *(const uint4*)(smu + FO_M + wm * 64 + lane * 32 + 16);
        const bool anymask = __any_sync(0xffffffffu,
            (mA.x | mA.y | mA.z | mA.w | mB.x | mB.y | mB.z | mB.w) != 0);

        // ---- S = Q K^T (bf16x3): load all frags, then term-major MMAs ----
        float sc[8][4];
#pragma unroll
        for (int j = 0; j < 8; j++)
#pragma unroll
            for (int e = 0; e < 4; e++) sc[j][e] = 0.f;

#pragma unroll
        for (int ks = 0; ks < 128; ks += 16) {
            uint32_t qh[4], ql[4], kh[4][4], kl[4][4];
            const uint32_t qaddr = sbase
                + (wm + ((lane >> 3) & 1) * 8 + (lane & 7)) * 272
                + (ks + ((lane >> 4) & 1) * 8) * 2;
            LDSM4(qh, qaddr);
            LDSM4(ql, qaddr + FO_QL);
#pragma unroll
            for (int g2 = 0; g2 < 4; g2++) {
                const uint32_t kaddr = sbase + FO_KV
                    + (g2 * 16 + ((lane >> 4) & 1) * 8 + (lane & 7)) * 272
                    + (ks + ((lane >> 3) & 1) * 8) * 2;
                LDSM4(kh[g2], kaddr);
                LDSM4(kl[g2], kaddr + 17408);
            }
#pragma unroll
            for (int g2 = 0; g2 < 4; g2++) {
                mma16816(sc[2 * g2],     qh, kh[g2][0], kh[g2][1]);
                mma16816(sc[2 * g2 + 1], qh, kh[g2][2], kh[g2][3]);
            }
#pragma unroll
            for (int g2 = 0; g2 < 4; g2++) {
                mma16816(sc[2 * g2],     qh, kl[g2][0], kl[g2][1]);
                mma16816(sc[2 * g2 + 1], qh, kl[g2][2], kl[g2][3]);
            }
#pragma unroll
            for (int g2 = 0; g2 < 4; g2++) {
                mma16816(sc[2 * g2],     ql, kh[g2][0], kh[g2][1]);
                mma16816(sc[2 * g2 + 1], ql, kh[g2][2], kh[g2][3]);
            }
        }
        __syncthreads();   // K consumed; buffer free for V

        // ---- issue V load (overlaps softmax) ----
#pragma unroll
        for (int i = tid; i < 2048; i += 128) {
            const int t = i >> 10, r = (i >> 4) & 63, c = i & 15;
            const __nv_bfloat16* g = (t ? g_Vl : g_Vh) + bhoff
                + (size_t)(kt * 64 + r) * 128 + c * 8;
            CP_ASYNC_16(sbase + FO_KV + t * 17408 + r * 272 + c * 16, g);
        }
        CP_COMMIT();

        // ---- register softmax + P packing ----
        uint32_t pha[16], pla[16];
        float l0a = 0.f, l1a = 0.f;
#pragma unroll
        for (int j = 0; j < 8; j++) {
            float s0 = sc[j][0] * ATT_SCALE, s1 = sc[j][1] * ATT_SCALE;
            float s2 = sc[j][2] * ATT_SCALE, s3 = sc[j][3] * ATT_SCALE;
            if (anymask) {
                const int c0 = 8 * j + 2 * t4;
                if (smu[FO_M + (wm + g4) * 64 + c0])         s0 = -1e9f;
                if (smu[FO_M + (wm + g4) * 64 + c0 + 1])     s1 = -1e9f;
                if (smu[FO_M + (wm + g4 + 8) * 64 + c0])     s2 = -1e9f;
                if (smu[FO_M + (wm + g4 + 8) * 64 + c0 + 1]) s3 = -1e9f;
            }
            const float p0 = __expf(s0), p1 = __expf(s1);
            const float p2 = __expf(s2), p3 = __expf(s3);
            l0a += p0 + p1;
            l1a += p2 + p3;
            const float h0 = __bfloat162float(__float2bfloat16(p0));
            const float h1 = __bfloat162float(__float2bfloat16(p1));
            const float h2 = __bfloat162float(__float2bfloat16(p2));
            const float h3 = __bfloat162float(__float2bfloat16(p3));
            const int base = 4 * (j >> 1) + (j & 1) * 2;
            pha[base]     = pk2(p0, p1);
            pha[base + 1] = pk2(p2, p3);
            pla[base]     = pk2(p0 - h0, p1 - h1);
            pla[base + 1] = pk2(p2 - h2, p3 - h3);
        }
        l0a += __shfl_xor_sync(0xffffffffu, l0a, 1);
        l0a += __shfl_xor_sync(0xffffffffu, l0a, 2);
        l1a += __shfl_xor_sync(0xffffffffu, l1a, 1);
        l1a += __shfl_xor_sync(0xffffffffu, l1a, 2);
        l0 += l0a;
        l1 += l1a;

        CP_WAIT(0);
        __syncthreads();   // V ready; mask consumed

        // ---- O += P V, first half (q = 0,1: V rows 0..31) ----
#pragma unroll
        for (int q = 0; q < 2; q++) {
#pragma unroll
            for (int h2b = 0; h2b < 8; h2b += 4) {
                uint32_t vh[4][4], vl[4][4];
#pragma unroll
                for (int j = 0; j < 4; j++) {
                    const int h2 = h2b + j;
                    const uint32_t vaddr = sbase + FO_KV
                        + (16 * q + ((lane >> 3) & 1) * 8 + (lane & 7)) * 272
                        + (16 * h2 + ((lane >> 4) & 1) * 8) * 2;
                    LDSM4T(vh[j], vaddr);
                    LDSM4T(vl[j], vaddr + 17408);
                }
#pragma unroll
                for (int j = 0; j < 4; j++) {
                    const int h2 = h2b + j;
                    mma16816(oacc[2 * h2],     &pha[4 * q], vh[j][0], vh[j][1]);
                    mma16816(oacc[2 * h2 + 1], &pha[4 * q], vh[j][2], vh[j][3]);
                }
#pragma unroll
                for (int j = 0; j < 4; j++) {
                    const int h2 = h2b + j;
                    mma16816(oacc[2 * h2],     &pha[4 * q], vl[j][0], vl[j][1]);
                    mma16816(oacc[2 * h2 + 1], &pha[4 * q], vl[j][2], vl[j][3]);
                }
#pragma unroll
                for (int j = 0; j < 4; j++) {
                    const int h2 = h2b + j;
                    mma16816(oacc[2 * h2],     &pla[4 * q], vh[j][0], vh[j][1]);
                    mma16816(oacc[2 * h2 + 1], &pla[4 * q], vh[j][2], vh[j][3]);
                }
            }
        }
        __syncthreads();   // V rows 0..31 consumed by all warps

        // ---- issue K(t+1) rows 0..31 + mask(t+1) (overlaps PV 2nd half) ----
        if (kt + 1 < 32) {
#pragma unroll
            for (int i = tid; i < 1024; i += 128) {
                const int t = i >> 9, r = (i >> 4) & 31, c = i & 15;
                const __nv_bfloat16* g = (t ? g_Kl : g_Kh) + bhoff
                    + (size_t)((kt + 1) * 64 + r) * 128 + c * 8;
                CP_ASYNC_16(sbase + FO_KV + t * 17408 + r * 272 + c * 16, g);
            }
#pragma unroll
            for (int i = tid; i < 256; i += 128) {
                const int r = i >> 2, c = i & 3;
                CP_ASYNC_16(sbase + FO_M + r * 64 + c * 16,
                            mask + mbase + (size_t)r * NL + (kt + 1) * 64 + c * 16);
            }
            CP_COMMIT();
        }

        // ---- O += P V, second half (q = 2,3: V rows 32..63) ----
#pragma unroll
        for (int q = 2; q < 4; q++) {
#pragma unroll
            for (int h2b = 0; h2b < 8; h2b += 4) {
                uint32_t vh[4][4], vl[4][4];
#pragma unroll
                for (int j = 0; j < 4; j++) {
                    const int h2 = h2b + j;
                    const uint32_t vaddr = sbase + FO_KV
                        + (16 * q + ((lane >> 3) & 1) * 8 + (lane & 7)) * 272
                        + (16 * h2 + ((lane >> 4) & 1) * 8) * 2;
                    LDSM4T(vh[j], vaddr);
                    LDSM4T(vl[j], vaddr + 17408);
                }
#pragma unroll
                for (int j = 0; j < 4; j++) {
                    const int h2 = h2b + j;
                    mma16816(oacc[2 * h2],     &pha[4 * q], vh[j][0], vh[j][1]);
                    mma16816(oacc[2 * h2 + 1], &pha[4 * q], vh[j][2], vh[j][3]);
                }
#pragma unroll
                for (int j = 0; j < 4; j++) {
                    const int h2 = h2b + j;
                    mma16816(oacc[2 * h2],     &pha[4 * q], vl[j][0], vl[j][1]);
                    mma16816(oacc[2 * h2 + 1], &pha[4 * q], vl[j][2], vl[j][3]);
                }
#pragma unroll
                for (int j = 0; j < 4; j++) {
                    const int h2 = h2b + j;
                    mma16816(oacc[2 * h2],     &pla[4 * q], vh[j][0], vh[j][1]);
                    mma16816(oacc[2 * h2 + 1], &pla[4 * q], vh[j][2], vh[j][3]);
                }
            }
        }
        __syncthreads();   // V rows 32..63 consumed

        // ---- issue K(t+1) rows 32..63 ----
        if (kt + 1 < 32) {
#pragma unroll
            for (int i = tid; i < 1024; i += 128) {
                const int t = i >> 9, r = 32 + ((i >> 4) & 31), c = i & 15;
                const __nv_bfloat16* g = (t ? g_Kl : g_Kh) + bhoff
                    + (size_t)((kt + 1) * 64 + r) * 128 + c * 8;
                CP_ASYNC_16(sbase + FO_KV + t * 17408 + r * 272 + c * 16, g);
            }
            CP_COMMIT();
        }
    }

    // ---- epilogue: normalize, split, write ctx from registers ----
    const float inv0 = 1.f / l0, inv1 = 1.f / l1;
    const size_t row0 = (size_t)(b * NL + q0 + wm + g4);
    const size_t o0 = row0 * 1024 + h * 128 + 2 * t4;
    const size_t o1 = o0 + 8 * 1024;
#pragma unroll
    for (int j = 0; j < 16; j++) {
        const float v0 = oacc[j][0] * inv0, v1 = oacc[j][1] * inv0;
        const float v2 = oacc[j][2] * inv1, v3 = oacc[j][3] * inv1;
        const __nv_bfloat162 h0 = __floats2bfloat162_rn(v0, v1);
        const __nv_bfloat162 h2 = __floats2bfloat162_rn(v2, v3);
        *(__nv_bfloat162*)(g_Ch + o0 + 8 * j) = h0;
        *(__nv_bfloat162*)(g_Ch + o1 + 8 * j) = h2;
        const __nv_bfloat162 r0 = __floats2bfloat162_rn(
            v0 - __bfloat162float(h0.x), v1 - __bfloat162float(h0.y));
        const __nv_bfloat162 r2 = __floats2bfloat162_rn(
            v2 - __bfloat162float(h2.x), v3 - __bfloat162float(h2.y));
        *(__nv_bfloat162*)(g_Cl + o0 + 8 * j) = r0;
        *(__nv_bfloat162*)(g_Cl + o1 + 8 * j) = r2;
    }
}

// ---------------------------------------------------------------------------
extern "C" void kernel_launch(void* const* d_in, const int* in_sizes, int n_in,
                              void* d_out, int out_size)
{
    const float* qIn  = (const float*)d_in[0];
    const float* kvIn = (const float*)d_in[1];
    const unsigned char* mask = (const unsigned char*)d_in[2];
    const float* W_Q  = (const float*)d_in[3];
    const float* W_K  = (const float*)d_in[4];
    const float* W_V  = (const float*)d_in[5];
    const float* W_fc = (const float*)d_in[6];
    float* out = (float*)d_out;

    __nv_bfloat16 *pXqh, *pXql, *pXkh, *pXkl;
    __nv_bfloat16 *pWQh, *pWQl, *pWKVh, *pWKVl, *pWFh, *pWFl;
    __nv_bfloat16 *pQh, *pQl, *pCh, *pCl;
    cudaGetSymbolAddress((void**)&pXqh, g_Xqh);   cudaGetSymbolAddress((void**)&pXql, g_Xql);
    cudaGetSymbolAddress((void**)&pXkh, g_Xkh);   cudaGetSymbolAddress((void**)&pXkl, g_Xkl);
    cudaGetSymbolAddress((void**)&pWQh, g_WQh);   cudaGetSymbolAddress((void**)&pWQl, g_WQl);
    cudaGetSymbolAddress((void**)&pWKVh, g_WKVh); cudaGetSymbolAddress((void**)&pWKVl, g_WKVl);
    cudaGetSymbolAddress((void**)&pWFh, g_WFh);   cudaGetSymbolAddress((void**)&pWFl, g_WFl);
    cudaGetSymbolAddress((void**)&pQh,  g_Qh);    cudaGetSymbolAddress((void**)&pQl,  g_Ql);
    cudaGetSymbolAddress((void**)&pCh,  g_Ch);    cudaGetSymbolAddress((void**)&pCl,  g_Cl);

    const int NTOT = NM * NE;
    const int SMEM_GEMM = 2 * GCHUNK2;   // 61440
    cudaFuncSetAttribute(gemm_kernel<0>, cudaFuncAttributeMaxDynamicSharedMemorySize, SMEM_GEMM);
    cudaFuncSetAttribute(gemm_kernel<1>, cudaFuncAttributeMaxDynamicSharedMemorySize, SMEM_GEMM);
    cudaFuncSetAttribute(gemm_kernel<4>, cudaFuncAttributeMaxDynamicSharedMemorySize, SMEM_GEMM);
    cudaFuncSetAttribute(flash_kernel,   cudaFuncAttributeMaxDynamicSharedMemorySize, FSMEM);

    // 1) splits
    split2_kernel<<<dim3(NTOT / 1024, 2), 256>>>(qIn, kvIn, NTOT / 4);
    transpose_split4_kernel<<<dim3(32, 32, 4), dim3(32, 8)>>>(W_Q, W_K, W_V, W_fc);

    // 2) projections: Q (N=1024) and fused K|V (N=2048)
    gemm_kernel<1><<<dim3(8, 128), 128, SMEM_GEMM>>>(
        pXqh, pXql, pWQh, pWQl, nullptr, pQh, pQl, 1024, 1024, 1024, 0);
    gemm_kernel<4><<<dim3(16, 128), 128, SMEM_GEMM>>>(
        pXkh, pXkl, pWKVh, pWKVl, nullptr, nullptr, nullptr, 1024, 1024, 1024, 0);

    // 3) fused attention -> split ctx [b*l, h*128+d]
    flash_kernel<<<dim3(32, 32), 128, FSMEM>>>(mask);

    // 4) out = ctx W_fc
    gemm_kernel<0><<<dim3(8, 128), 128, SMEM_GEMM>>>(
        pCh, pCl, pWFh, pWFl, out, nullptr, nullptr, 1024, 1024, 1024, 1024);
}